// round 1
// baseline (speedup 1.0000x reference)
#include <cuda_runtime.h>

#define BB 4096
#define MAXN 12
#define HID 301
#define NT 10
#define PP 9
#define VSTAT 310   // HID + PP

// ---------------- scratch (device globals; no allocations allowed) ----------
__device__ float d_g[(size_t)BB * 11 * HID];   // gated vectors per node 0..10
__device__ float d_hcur[(size_t)BB * HID];     // current node hidden state
__device__ float d_hin[(size_t)BB * HID];      // aggregated message

__device__ __forceinline__ float sigm(float x) { return 1.f / (1.f + __expf(-x)); }

// ---------------- node 0: h0 = gru(x0, 0) ----------------------------------
__global__ void k_h0(const int* __restrict__ types, const int* __restrict__ paths,
                     const float* __restrict__ W_ih, const float* __restrict__ b_ih,
                     const float* __restrict__ b_hh)
{
    int idx = blockIdx.x * blockDim.x + threadIdx.x;
    if (idx >= BB * HID) return;
    int b = idx / HID, j = idx - b * HID;
    int t = types[b * MAXN], p = paths[b * MAXN];
    float ir  = W_ih[j * 19 + t]            + W_ih[j * 19 + NT + p]            + b_ih[j];
    float iz  = W_ih[(j + HID) * 19 + t]    + W_ih[(j + HID) * 19 + NT + p]    + b_ih[j + HID];
    float inn = W_ih[(j + 2*HID) * 19 + t]  + W_ih[(j + 2*HID) * 19 + NT + p]  + b_ih[j + 2*HID];
    float r = sigm(ir + b_hh[j]);
    float z = sigm(iz + b_hh[j + HID]);
    float n = tanhf(inn + r * b_hh[j + 2*HID]);
    d_hcur[idx] = (1.f - z) * n;   // h_prev = 0
}

// ---------------- h_in[b] = sum_{u<v} adj[b,v,u] * g[b,u] ------------------
__global__ void k_hin(const int* __restrict__ adj, int v)
{
    int b = blockIdx.x;
    __shared__ float a[MAXN];
    int j = threadIdx.x;
    if (j < v) a[j] = (float)adj[b * (MAXN * MAXN) + v * MAXN + j];
    __syncthreads();
    if (j >= HID) return;
    const float* gb = d_g + (size_t)b * 11 * HID;
    float acc = 0.f;
    for (int u = 0; u < v; ++u) {
        float av = a[u];                 // warp-uniform
        if (av != 0.f) acc += gb[u * HID + j];
    }
    d_hin[b * HID + j] = acc;
}

// ---------------- fused GRU step: h = gru(x_v, h_in) -----------------------
// Tile: 64 batch rows x 32 outputs, K=301 over h_in. 3 accumulators (r,z,n).
__global__ void __launch_bounds__(256) k_gru(int v,
    const int* __restrict__ types, const int* __restrict__ paths,
    const float* __restrict__ W_ih, const float* __restrict__ W_hh,
    const float* __restrict__ b_ih, const float* __restrict__ b_hh)
{
    __shared__ float sH[64][33];
    __shared__ float sW[3][32][33];
    int tid = threadIdx.x;
    int tx = tid & 31, ty = tid >> 5;
    int b0 = blockIdx.x * 64;
    int j0 = blockIdx.y * 32;

    float ar[8], az[8], an[8];
#pragma unroll
    for (int i = 0; i < 8; ++i) { ar[i] = 0.f; az[i] = 0.f; an[i] = 0.f; }

    for (int k0 = 0; k0 < HID; k0 += 32) {
        int k = k0 + tx;
#pragma unroll
        for (int i = 0; i < 8; ++i) {
            int row = ty + 8 * i;
            sH[row][tx] = (k < HID) ? d_hin[(b0 + row) * HID + k] : 0.f;
        }
#pragma unroll
        for (int s = 0; s < 3; ++s)
#pragma unroll
            for (int i = 0; i < 4; ++i) {
                int jj = ty + 8 * i;
                int j = j0 + jj;
                sW[s][jj][tx] = (j < HID && k < HID) ? W_hh[(s * HID + j) * HID + k] : 0.f;
            }
        __syncthreads();
#pragma unroll
        for (int kk = 0; kk < 32; ++kk) {
            float wr = sW[0][tx][kk], wz = sW[1][tx][kk], wn = sW[2][tx][kk];
#pragma unroll
            for (int i = 0; i < 8; ++i) {
                float hv = sH[ty + 8 * i][kk];
                ar[i] = fmaf(hv, wr, ar[i]);
                az[i] = fmaf(hv, wz, az[i]);
                an[i] = fmaf(hv, wn, an[i]);
            }
        }
        __syncthreads();
    }

    int j = j0 + tx;
    if (j < HID) {
        float bir = b_ih[j], biz = b_ih[j + HID], bin_ = b_ih[j + 2*HID];
        float bhr = b_hh[j], bhz = b_hh[j + HID], bhn = b_hh[j + 2*HID];
        const float* wr_row = W_ih + j * 19;
        const float* wz_row = W_ih + (j + HID) * 19;
        const float* wn_row = W_ih + (j + 2*HID) * 19;
#pragma unroll
        for (int i = 0; i < 8; ++i) {
            int b = b0 + ty + 8 * i;
            int t = types[b * MAXN + v], p = paths[b * MAXN + v];
            float ir  = wr_row[t] + wr_row[NT + p] + bir;
            float iz  = wz_row[t] + wz_row[NT + p] + biz;
            float inn = wn_row[t] + wn_row[NT + p] + bin_;
            float r = sigm(ir + ar[i] + bhr);
            float z = sigm(iz + az[i] + bhz);
            float n = tanhf(inn + r * (an[i] + bhn));
            float hi = d_hin[b * HID + j];
            d_hcur[b * HID + j] = (1.f - z) * n + z * hi;
        }
    }
}

// ---------------- fused gate: g[b,v] = sigmoid(ps@Wg.T+bg) * (ps@Wm.T) -----
__global__ void __launch_bounds__(256) k_gate(int v,
    const int* __restrict__ paths,
    const float* __restrict__ Wg, const float* __restrict__ bg,
    const float* __restrict__ Wm)
{
    __shared__ float sH[64][33];
    __shared__ float sW[2][32][33];
    int tid = threadIdx.x;
    int tx = tid & 31, ty = tid >> 5;
    int b0 = blockIdx.x * 64;
    int j0 = blockIdx.y * 32;

    float ag[8], am[8];
#pragma unroll
    for (int i = 0; i < 8; ++i) { ag[i] = 0.f; am[i] = 0.f; }

    for (int k0 = 0; k0 < HID; k0 += 32) {
        int k = k0 + tx;
#pragma unroll
        for (int i = 0; i < 8; ++i) {
            int row = ty + 8 * i;
            sH[row][tx] = (k < HID) ? d_hcur[(b0 + row) * HID + k] : 0.f;
        }
#pragma unroll
        for (int i = 0; i < 4; ++i) {
            int jj = ty + 8 * i;
            int j = j0 + jj;
            bool ok = (j < HID && k < HID);
            sW[0][jj][tx] = ok ? Wg[j * VSTAT + k] : 0.f;
            sW[1][jj][tx] = ok ? Wm[j * VSTAT + k] : 0.f;
        }
        __syncthreads();
#pragma unroll
        for (int kk = 0; kk < 32; ++kk) {
            float wg = sW[0][tx][kk], wm = sW[1][tx][kk];
#pragma unroll
            for (int i = 0; i < 8; ++i) {
                float hv = sH[ty + 8 * i][kk];
                ag[i] = fmaf(hv, wg, ag[i]);
                am[i] = fmaf(hv, wm, am[i]);
            }
        }
        __syncthreads();
    }

    int j = j0 + tx;
    if (j < HID) {
        float bgj = bg[j];
        const float* wg_row = Wg + j * VSTAT + HID;  // positional one-hot columns
        const float* wm_row = Wm + j * VSTAT + HID;
#pragma unroll
        for (int i = 0; i < 8; ++i) {
            int b = b0 + ty + 8 * i;
            int p = paths[b * MAXN + v];
            float gv = sigm(ag[i] + wg_row[p] + bgj);
            float mv = am[i] + wm_row[p];
            d_g[((size_t)b * 11 + v) * HID + j] = gv * mv;
        }
    }
}

// ---------------- head: df scatter + 2 tiny MLPs + fc1/fc2 -----------------
__global__ void __launch_bounds__(128) k_head(
    const int* __restrict__ paths, const float* __restrict__ feats,
    const float* __restrict__ W_df1, const float* __restrict__ b_df1,
    const float* __restrict__ W_df2, const float* __restrict__ b_df2,
    const float* __restrict__ W_fc1, const float* __restrict__ b_fc1,
    const float* __restrict__ W_fc2, const float* __restrict__ b_fc2,
    float* __restrict__ out)
{
    int b = blockIdx.x;
    int t = threadIdx.x;
    __shared__ float hg[HID + 8];
    __shared__ float df[3 * PP];
    __shared__ float hid16[16];

    for (int j = t; j < HID; j += 128) hg[j] = d_hcur[b * HID + j];
    if (t < 3 * PP) df[t] = 0.f;
    __syncthreads();
    if (t == 0) {
        // sequential scatter: later v overwrites (matches reference order)
        for (int v = 0; v < MAXN; ++v) {
            int base = paths[b * MAXN + v] * 3;
            df[base]     = feats[(b * MAXN + v) * 3 + 0];
            df[base + 1] = feats[(b * MAXN + v) * 3 + 1];
            df[base + 2] = feats[(b * MAXN + v) * 3 + 2];
        }
    }
    __syncthreads();
    if (t < 16) {
        float a = b_df1[t];
        for (int k = 0; k < 3 * PP; ++k) a = fmaf(df[k], W_df1[t * (3 * PP) + k], a);
        hid16[t] = fmaxf(a, 0.f);
    }
    __syncthreads();
    if (t < 8) {
        float a = b_df2[t];
        for (int k = 0; k < 16; ++k) a = fmaf(hid16[k], W_df2[t * 16 + k], a);
        hg[HID + t] = a;
    }
    __syncthreads();
    if (t < 112) {
        const float* W;
        float a;
        int i;
        if (t < 56) { i = t;      W = W_fc1; a = b_fc1[i]; }
        else        { i = t - 56; W = W_fc2; a = b_fc2[i]; }
        const float* wrow = W + i * (HID + 8);
        for (int k = 0; k < HID + 8; ++k) a = fmaf(hg[k], wrow[k], a);
        out[b * 112 + t] = a;
    }
}

// ---------------- launcher --------------------------------------------------
extern "C" void kernel_launch(void* const* d_in, const int* in_sizes, int n_in,
                              void* d_out, int out_size)
{
    const int*   types = (const int*)d_in[0];
    const int*   paths = (const int*)d_in[1];
    const int*   adj   = (const int*)d_in[2];
    const float* feats = (const float*)d_in[3];
    const float* W_ih  = (const float*)d_in[4];
    const float* W_hh  = (const float*)d_in[5];
    const float* b_ih  = (const float*)d_in[6];
    const float* b_hh  = (const float*)d_in[7];
    const float* Wg    = (const float*)d_in[8];
    const float* bg    = (const float*)d_in[9];
    const float* Wm    = (const float*)d_in[10];
    const float* W_df1 = (const float*)d_in[11];
    const float* b_df1 = (const float*)d_in[12];
    const float* W_df2 = (const float*)d_in[13];
    const float* b_df2 = (const float*)d_in[14];
    const float* W_fc1 = (const float*)d_in[15];
    const float* b_fc1 = (const float*)d_in[16];
    const float* W_fc2 = (const float*)d_in[17];
    const float* b_fc2 = (const float*)d_in[18];
    float* out = (float*)d_out;

    dim3 gemmGrid(BB / 64, (HID + 31) / 32);

    k_h0<<<(BB * HID + 255) / 256, 256>>>(types, paths, W_ih, b_ih, b_hh);
    k_gate<<<gemmGrid, 256>>>(0, paths, Wg, bg, Wm);
    for (int v = 1; v < MAXN; ++v) {
        k_hin<<<BB, 320>>>(adj, v);
        k_gru<<<gemmGrid, 256>>>(v, types, paths, W_ih, W_hh, b_ih, b_hh);
        if (v < MAXN - 1)
            k_gate<<<gemmGrid, 256>>>(v, paths, Wg, bg, Wm);
    }
    k_head<<<BB, 128>>>(paths, feats, W_df1, b_df1, W_df2, b_df2,
                        W_fc1, b_fc1, W_fc2, b_fc2, out);
}

// round 2
// speedup vs baseline: 1.2726x; 1.2726x over previous
#include <cuda_runtime.h>

#define BB 4096
#define MAXN 12
#define HID 301
#define NT 10
#define PP 9
#define VSTAT 310   // HID + PP
#define KP 320      // padded K / hidden stride (10 k-blocks of 32)
#define KP4 80      // KP/4

// ---------------- scratch (device globals; zero-initialized, pads never written)
__device__ float d_g[(size_t)BB * 11 * KP];    // gated vectors per node 0..10
__device__ float d_hcur[(size_t)BB * KP];      // current node hidden state
__device__ float d_hin[(size_t)BB * KP];       // aggregated message
__device__ float d_Whh[3 * KP * KP];           // padded W_hh  [3][320][320]
__device__ float d_Wgm[2 * KP * KP];           // padded Wg,Wm [2][320][320]

__device__ __forceinline__ float sigm(float x) { return 1.f / (1.f + __expf(-x)); }

// ---------------- weight repack (zero pads stay zero forever) ---------------
__global__ void k_pad(const float* __restrict__ Whh, const float* __restrict__ Wg,
                      const float* __restrict__ Wm)
{
    int idx = blockIdx.x * blockDim.x + threadIdx.x;
    const int total = HID * HID;
    if (idx < 3 * total) {
        int s = idx / total, r = idx - s * total, j = r / HID, k = r - j * HID;
        d_Whh[(s * KP + j) * KP + k] = Whh[(s * HID + j) * HID + k];
    } else if (idx < 5 * total) {
        int m = (idx - 3 * total) / total, r = (idx - 3 * total) % total;
        int j = r / HID, k = r - j * HID;
        const float* W = m ? Wm : Wg;
        d_Wgm[(m * KP + j) * KP + k] = W[j * VSTAT + k];
    }
}

// ---------------- node 0: h0 = gru(x0, 0) ----------------------------------
__global__ void k_h0(const int* __restrict__ types, const int* __restrict__ paths,
                     const float* __restrict__ W_ih, const float* __restrict__ b_ih,
                     const float* __restrict__ b_hh)
{
    int idx = blockIdx.x * blockDim.x + threadIdx.x;
    if (idx >= BB * HID) return;
    int b = idx / HID, j = idx - b * HID;
    int t = types[b * MAXN], p = paths[b * MAXN];
    float ir  = W_ih[j * 19 + t]            + W_ih[j * 19 + NT + p]            + b_ih[j];
    float iz  = W_ih[(j + HID) * 19 + t]    + W_ih[(j + HID) * 19 + NT + p]    + b_ih[j + HID];
    float inn = W_ih[(j + 2*HID) * 19 + t]  + W_ih[(j + 2*HID) * 19 + NT + p]  + b_ih[j + 2*HID];
    float r = sigm(ir + b_hh[j]);
    float z = sigm(iz + b_hh[j + HID]);
    float n = tanhf(inn + r * b_hh[j + 2*HID]);
    d_hcur[(size_t)b * KP + j] = (1.f - z) * n;   // h_prev = 0
}

// ---------------- h_in[b] = sum_{u<v} adj[b,v,u] * g[b,u]  (float4) --------
__global__ void k_hin(const int* __restrict__ adj, int v)
{
    int t = threadIdx.x;          // 0..319
    int lb = t / KP4, c4 = t - lb * KP4;
    int b = blockIdx.x * 4 + lb;
    const float4* g4 = (const float4*)d_g;
    const int* arow = adj + b * (MAXN * MAXN) + v * MAXN;
    float4 acc = make_float4(0.f, 0.f, 0.f, 0.f);
    for (int u = 0; u < v; ++u) {
        if (arow[u]) {
            float4 gv = g4[((size_t)b * 11 + u) * KP4 + c4];
            acc.x += gv.x; acc.y += gv.y; acc.z += gv.z; acc.w += gv.w;
        }
    }
    ((float4*)d_hin)[(size_t)b * KP4 + c4] = acc;
}

// ---------------- fused GRU step: h = gru(x_v, h_in) -----------------------
// Tile: 64 batch x 32 outputs x 3 gates. K padded to 320, all LDS/LDG float4.
__global__ void __launch_bounds__(256) k_gru(int v,
    const int* __restrict__ types, const int* __restrict__ paths,
    const float* __restrict__ W_ih,
    const float* __restrict__ b_ih, const float* __restrict__ b_hh)
{
    __shared__ float4 sH4[64][8];
    __shared__ float4 sW4[3][32][9];   // stride 9 float4 = 36 floats (conflict-free)
    int tid = threadIdx.x;
    int tx = tid & 31, ty = tid >> 5;
    int b0 = blockIdx.x * 64;
    int j0 = blockIdx.y * 32;

    float ar[8], az[8], an[8];
#pragma unroll
    for (int i = 0; i < 8; ++i) { ar[i] = 0.f; az[i] = 0.f; an[i] = 0.f; }

    const float4* hin4 = (const float4*)d_hin;

    for (int k0 = 0; k0 < KP; k0 += 32) {
        int kq0 = k0 >> 2;
#pragma unroll
        for (int q = 0; q < 2; ++q) {
            int idx = tid + 256 * q;
            int row = idx >> 3, c4 = idx & 7;
            sH4[row][c4] = hin4[(size_t)(b0 + row) * KP4 + kq0 + c4];
        }
#pragma unroll
        for (int q = 0; q < 3; ++q) {
            int idx = tid + 256 * q;
            int srow = idx >> 3, c4 = idx & 7;
            int s = srow >> 5, jj = srow & 31;
            sW4[s][jj][c4] =
                *(const float4*)&d_Whh[((s * KP) + (j0 + jj)) * KP + k0 + 4 * c4];
        }
        __syncthreads();
#pragma unroll
        for (int kq = 0; kq < 8; ++kq) {
            float4 wr = sW4[0][tx][kq], wz = sW4[1][tx][kq], wn = sW4[2][tx][kq];
#pragma unroll
            for (int i = 0; i < 8; ++i) {
                float4 h = sH4[ty + 8 * i][kq];
                ar[i] = fmaf(h.x, wr.x, ar[i]); ar[i] = fmaf(h.y, wr.y, ar[i]);
                ar[i] = fmaf(h.z, wr.z, ar[i]); ar[i] = fmaf(h.w, wr.w, ar[i]);
                az[i] = fmaf(h.x, wz.x, az[i]); az[i] = fmaf(h.y, wz.y, az[i]);
                az[i] = fmaf(h.z, wz.z, az[i]); az[i] = fmaf(h.w, wz.w, az[i]);
                an[i] = fmaf(h.x, wn.x, an[i]); an[i] = fmaf(h.y, wn.y, an[i]);
                an[i] = fmaf(h.z, wn.z, an[i]); an[i] = fmaf(h.w, wn.w, an[i]);
            }
        }
        __syncthreads();
    }

    int j = j0 + tx;
    if (j < HID) {
        float bir = b_ih[j], biz = b_ih[j + HID], bin_ = b_ih[j + 2*HID];
        float bhr = b_hh[j], bhz = b_hh[j + HID], bhn = b_hh[j + 2*HID];
        const float* wr_row = W_ih + j * 19;
        const float* wz_row = W_ih + (j + HID) * 19;
        const float* wn_row = W_ih + (j + 2*HID) * 19;
#pragma unroll
        for (int i = 0; i < 8; ++i) {
            int b = b0 + ty + 8 * i;
            int t = types[b * MAXN + v], p = paths[b * MAXN + v];
            float ir  = wr_row[t] + wr_row[NT + p] + bir;
            float iz  = wz_row[t] + wz_row[NT + p] + biz;
            float inn = wn_row[t] + wn_row[NT + p] + bin_;
            float r = sigm(ir + ar[i] + bhr);
            float z = sigm(iz + az[i] + bhz);
            float n = tanhf(inn + r * (an[i] + bhn));
            float hi = d_hin[(size_t)b * KP + j];
            d_hcur[(size_t)b * KP + j] = (1.f - z) * n + z * hi;
        }
    }
}

// ---------------- fused gate: g[b,v] = sigmoid(ps@Wg.T+bg) * (ps@Wm.T) -----
__global__ void __launch_bounds__(256) k_gate(int v,
    const int* __restrict__ paths,
    const float* __restrict__ Wg, const float* __restrict__ bg,
    const float* __restrict__ Wm)
{
    __shared__ float4 sH4[64][8];
    __shared__ float4 sW4[2][32][9];
    int tid = threadIdx.x;
    int tx = tid & 31, ty = tid >> 5;
    int b0 = blockIdx.x * 64;
    int j0 = blockIdx.y * 32;

    float ag[8], am[8];
#pragma unroll
    for (int i = 0; i < 8; ++i) { ag[i] = 0.f; am[i] = 0.f; }

    const float4* h4 = (const float4*)d_hcur;

    for (int k0 = 0; k0 < KP; k0 += 32) {
        int kq0 = k0 >> 2;
#pragma unroll
        for (int q = 0; q < 2; ++q) {
            int idx = tid + 256 * q;
            int row = idx >> 3, c4 = idx & 7;
            sH4[row][c4] = h4[(size_t)(b0 + row) * KP4 + kq0 + c4];
        }
#pragma unroll
        for (int q = 0; q < 2; ++q) {
            int idx = tid + 256 * q;
            int srow = idx >> 3, c4 = idx & 7;
            int s = srow >> 5, jj = srow & 31;
            sW4[s][jj][c4] =
                *(const float4*)&d_Wgm[((s * KP) + (j0 + jj)) * KP + k0 + 4 * c4];
        }
        __syncthreads();
#pragma unroll
        for (int kq = 0; kq < 8; ++kq) {
            float4 wg = sW4[0][tx][kq], wm = sW4[1][tx][kq];
#pragma unroll
            for (int i = 0; i < 8; ++i) {
                float4 h = sH4[ty + 8 * i][kq];
                ag[i] = fmaf(h.x, wg.x, ag[i]); ag[i] = fmaf(h.y, wg.y, ag[i]);
                ag[i] = fmaf(h.z, wg.z, ag[i]); ag[i] = fmaf(h.w, wg.w, ag[i]);
                am[i] = fmaf(h.x, wm.x, am[i]); am[i] = fmaf(h.y, wm.y, am[i]);
                am[i] = fmaf(h.z, wm.z, am[i]); am[i] = fmaf(h.w, wm.w, am[i]);
            }
        }
        __syncthreads();
    }

    int j = j0 + tx;
    if (j < HID) {
        float bgj = bg[j];
        const float* wg_row = Wg + j * VSTAT + HID;  // positional one-hot columns
        const float* wm_row = Wm + j * VSTAT + HID;
#pragma unroll
        for (int i = 0; i < 8; ++i) {
            int b = b0 + ty + 8 * i;
            int p = paths[b * MAXN + v];
            float gv = sigm(ag[i] + wg_row[p] + bgj);
            float mv = am[i] + wm_row[p];
            d_g[((size_t)b * 11 + v) * KP + j] = gv * mv;
        }
    }
}

// ---------------- head: df scatter + 2 tiny MLPs + fc1/fc2 -----------------
__global__ void __launch_bounds__(128) k_head(
    const int* __restrict__ paths, const float* __restrict__ feats,
    const float* __restrict__ W_df1, const float* __restrict__ b_df1,
    const float* __restrict__ W_df2, const float* __restrict__ b_df2,
    const float* __restrict__ W_fc1, const float* __restrict__ b_fc1,
    const float* __restrict__ W_fc2, const float* __restrict__ b_fc2,
    float* __restrict__ out)
{
    int b = blockIdx.x;
    int t = threadIdx.x;
    __shared__ float hg[HID + 8];
    __shared__ float df[3 * PP];
    __shared__ float hid16[16];

    for (int j = t; j < HID; j += 128) hg[j] = d_hcur[(size_t)b * KP + j];
    if (t < 3 * PP) df[t] = 0.f;
    __syncthreads();
    if (t == 0) {
        for (int v = 0; v < MAXN; ++v) {
            int base = paths[b * MAXN + v] * 3;
            df[base]     = feats[(b * MAXN + v) * 3 + 0];
            df[base + 1] = feats[(b * MAXN + v) * 3 + 1];
            df[base + 2] = feats[(b * MAXN + v) * 3 + 2];
        }
    }
    __syncthreads();
    if (t < 16) {
        float a = b_df1[t];
        for (int k = 0; k < 3 * PP; ++k) a = fmaf(df[k], W_df1[t * (3 * PP) + k], a);
        hid16[t] = fmaxf(a, 0.f);
    }
    __syncthreads();
    if (t < 8) {
        float a = b_df2[t];
        for (int k = 0; k < 16; ++k) a = fmaf(hid16[k], W_df2[t * 16 + k], a);
        hg[HID + t] = a;
    }
    __syncthreads();
    if (t < 112) {
        const float* W;
        float a;
        int i;
        if (t < 56) { i = t;      W = W_fc1; a = b_fc1[i]; }
        else        { i = t - 56; W = W_fc2; a = b_fc2[i]; }
        const float* wrow = W + i * (HID + 8);
        for (int k = 0; k < HID + 8; ++k) a = fmaf(hg[k], wrow[k], a);
        out[b * 112 + t] = a;
    }
}

// ---------------- launcher --------------------------------------------------
extern "C" void kernel_launch(void* const* d_in, const int* in_sizes, int n_in,
                              void* d_out, int out_size)
{
    const int*   types = (const int*)d_in[0];
    const int*   paths = (const int*)d_in[1];
    const int*   adj   = (const int*)d_in[2];
    const float* feats = (const float*)d_in[3];
    const float* W_ih  = (const float*)d_in[4];
    const float* W_hh  = (const float*)d_in[5];
    const float* b_ih  = (const float*)d_in[6];
    const float* b_hh  = (const float*)d_in[7];
    const float* Wg    = (const float*)d_in[8];
    const float* bg    = (const float*)d_in[9];
    const float* Wm    = (const float*)d_in[10];
    const float* W_df1 = (const float*)d_in[11];
    const float* b_df1 = (const float*)d_in[12];
    const float* W_df2 = (const float*)d_in[13];
    const float* b_df2 = (const float*)d_in[14];
    const float* W_fc1 = (const float*)d_in[15];
    const float* b_fc1 = (const float*)d_in[16];
    const float* W_fc2 = (const float*)d_in[17];
    const float* b_fc2 = (const float*)d_in[18];
    float* out = (float*)d_out;

    dim3 gemmGrid(BB / 64, 10);

    k_pad<<<(5 * HID * HID + 255) / 256, 256>>>(W_hh, Wg, Wm);
    k_h0<<<(BB * HID + 255) / 256, 256>>>(types, paths, W_ih, b_ih, b_hh);
    k_gate<<<gemmGrid, 256>>>(0, paths, Wg, bg, Wm);
    for (int v = 1; v < MAXN; ++v) {
        k_hin<<<BB / 4, 4 * KP4>>>(adj, v);
        k_gru<<<gemmGrid, 256>>>(v, types, paths, W_ih, b_ih, b_hh);
        if (v < MAXN - 1)
            k_gate<<<gemmGrid, 256>>>(v, paths, Wg, bg, Wm);
    }
    k_head<<<BB, 128>>>(paths, feats, W_df1, b_df1, W_df2, b_df2,
                        W_fc1, b_fc1, W_fc2, b_fc2, out);
}

// round 3
// speedup vs baseline: 1.3540x; 1.0639x over previous
#include <cuda_runtime.h>
#include <cstdint>

#define BB 4096
#define MAXN 12
#define HID 301
#define NT 10
#define PP 9
#define VSTAT 310   // HID + PP
#define KP 320      // padded K / hidden stride
#define KP4 80      // KP/4

// GEMM tile config
#define BM 128
#define BN 160
#define BK 32
#define SSTR 36     // smem row stride (floats): 16B-aligned v4 stores + conflict-free frags
#define SMEM_BYTES ((BM + BN) * SSTR * 2 * 4)

// ---------------- scratch (device globals; zero-initialized) ----------------
__device__ float d_g[(size_t)BB * 11 * KP];    // gated vectors per node 0..10
__device__ float d_hcur[(size_t)BB * KP];      // current node hidden state (fp32)
__device__ float d_hin[(size_t)BB * KP];       // aggregated message (fp32)
__device__ float d_A1[(size_t)BB * KP];        // tf32 split hi of current activation
__device__ float d_A2[(size_t)BB * KP];        // tf32 split lo
__device__ float d_Whh1[960 * KP];             // tf32 split of padded W_hh
__device__ float d_Whh2[960 * KP];
__device__ float d_Wgm1[640 * KP];             // tf32 split of padded [Wg;Wm]
__device__ float d_Wgm2[640 * KP];
__device__ float d_C[(size_t)BB * 960];        // raw GEMM output scratch

__device__ __forceinline__ float sigm(float x) { return 1.f / (1.f + __expf(-x)); }

__device__ __forceinline__ uint32_t f2tf32(float x) {
    uint32_t r; asm("cvt.rna.tf32.f32 %0, %1;" : "=r"(r) : "f"(x)); return r;
}
__device__ __forceinline__ void tf32split(float x, float& hi, float& lo) {
    uint32_t h = f2tf32(x);
    hi = __uint_as_float(h);
    lo = __uint_as_float(f2tf32(x - hi));
}

__device__ __forceinline__ void mma_tf32(float c[4], const uint32_t a[4],
                                         uint32_t b0, uint32_t b1) {
    asm volatile(
        "mma.sync.aligned.m16n8k8.row.col.f32.tf32.tf32.f32 "
        "{%0,%1,%2,%3}, {%4,%5,%6,%7}, {%8,%9}, {%0,%1,%2,%3};"
        : "+f"(c[0]), "+f"(c[1]), "+f"(c[2]), "+f"(c[3])
        : "r"(a[0]), "r"(a[1]), "r"(a[2]), "r"(a[3]), "r"(b0), "r"(b1));
}

// ---------------- weight repack + tf32 split (pads stay zero) ---------------
__global__ void k_pad(const float* __restrict__ Whh, const float* __restrict__ Wg,
                      const float* __restrict__ Wm)
{
    int idx = blockIdx.x * blockDim.x + threadIdx.x;
    const int total = HID * HID;
    if (idx < 3 * total) {
        int s = idx / total, r = idx - s * total, j = r / HID, k = r - j * HID;
        float hi, lo;
        tf32split(Whh[(s * HID + j) * HID + k], hi, lo);
        d_Whh1[(s * KP + j) * KP + k] = hi;
        d_Whh2[(s * KP + j) * KP + k] = lo;
    } else if (idx < 5 * total) {
        int m = (idx - 3 * total) / total, r = (idx - 3 * total) % total;
        int j = r / HID, k = r - j * HID;
        const float* W = m ? Wm : Wg;
        float hi, lo;
        tf32split(W[j * VSTAT + k], hi, lo);
        d_Wgm1[(m * KP + j) * KP + k] = hi;
        d_Wgm2[(m * KP + j) * KP + k] = lo;
    }
}

// ---------------- node 0: h0 = gru(x0, 0); emit splits ----------------------
__global__ void k_h0(const int* __restrict__ types, const int* __restrict__ paths,
                     const float* __restrict__ W_ih, const float* __restrict__ b_ih,
                     const float* __restrict__ b_hh)
{
    int idx = blockIdx.x * blockDim.x + threadIdx.x;
    if (idx >= BB * HID) return;
    int b = idx / HID, j = idx - b * HID;
    int t = types[b * MAXN], p = paths[b * MAXN];
    float ir  = W_ih[j * 19 + t]            + W_ih[j * 19 + NT + p]            + b_ih[j];
    float iz  = W_ih[(j + HID) * 19 + t]    + W_ih[(j + HID) * 19 + NT + p]    + b_ih[j + HID];
    float inn = W_ih[(j + 2*HID) * 19 + t]  + W_ih[(j + 2*HID) * 19 + NT + p]  + b_ih[j + 2*HID];
    float r = sigm(ir + b_hh[j]);
    float z = sigm(iz + b_hh[j + HID]);
    float n = tanhf(inn + r * b_hh[j + 2*HID]);
    float h = (1.f - z) * n;
    size_t o = (size_t)b * KP + j;
    d_hcur[o] = h;
    float hi, lo; tf32split(h, hi, lo);
    d_A1[o] = hi; d_A2[o] = lo;
}

// ---------------- h_in = sum adj*g ; emit fp32 + splits ---------------------
__global__ void k_hin(const int* __restrict__ adj, int v)
{
    int t = threadIdx.x;          // 0..319
    int lb = t / KP4, c4 = t - lb * KP4;
    int b = blockIdx.x * 4 + lb;
    const float4* g4 = (const float4*)d_g;
    const int* arow = adj + b * (MAXN * MAXN) + v * MAXN;
    float4 acc = make_float4(0.f, 0.f, 0.f, 0.f);
    for (int u = 0; u < v; ++u) {
        if (arow[u]) {
            float4 gv = g4[((size_t)b * 11 + u) * KP4 + c4];
            acc.x += gv.x; acc.y += gv.y; acc.z += gv.z; acc.w += gv.w;
        }
    }
    size_t o = (size_t)b * KP4 + c4;
    ((float4*)d_hin)[o] = acc;
    float4 h1, h2;
    tf32split(acc.x, h1.x, h2.x); tf32split(acc.y, h1.y, h2.y);
    tf32split(acc.z, h1.z, h2.z); tf32split(acc.w, h1.w, h2.w);
    ((float4*)d_A1)[o] = h1;
    ((float4*)d_A2)[o] = h2;
}

// ---------------- 3xTF32 GEMM: C[4096,N] = A[4096,320] @ W[N,320]^T ---------
__global__ void __launch_bounds__(256, 2) k_gemm(
    const float* __restrict__ Wt1, const float* __restrict__ Wt2,
    float* __restrict__ C, int N)
{
    extern __shared__ float smem[];
    float* sA1 = smem;
    float* sA2 = smem + BM * SSTR;
    float* sB1 = smem + 2 * BM * SSTR;
    float* sB2 = sB1 + BN * SSTR;

    int tid = threadIdx.x;
    int lane = tid & 31, wid = tid >> 5;
    int g = lane >> 2, tig = lane & 3;
    int wm = wid & 1, wn = wid >> 1;          // 2 x 4 warps
    int b0 = blockIdx.x * BM;
    int n0 = blockIdx.y * BN;

    float c[4][5][4];
#pragma unroll
    for (int mf = 0; mf < 4; ++mf)
#pragma unroll
        for (int nf = 0; nf < 5; ++nf)
#pragma unroll
            for (int i = 0; i < 4; ++i) c[mf][nf][i] = 0.f;

    for (int k0 = 0; k0 < KP; k0 += BK) {
        // load A tiles (128 x 32): 1024 float4
#pragma unroll
        for (int q = 0; q < 4; ++q) {
            int i = tid + 256 * q;
            int r = i >> 3, cc = i & 7;
            *(float4*)&sA1[r * SSTR + cc * 4] =
                *(const float4*)&d_A1[(size_t)(b0 + r) * KP + k0 + cc * 4];
            *(float4*)&sA2[r * SSTR + cc * 4] =
                *(const float4*)&d_A2[(size_t)(b0 + r) * KP + k0 + cc * 4];
        }
        // load B tiles (160 x 32): 1280 float4
#pragma unroll
        for (int q = 0; q < 5; ++q) {
            int i = tid + 256 * q;
            int r = i >> 3, cc = i & 7;
            *(float4*)&sB1[r * SSTR + cc * 4] =
                *(const float4*)&Wt1[(size_t)(n0 + r) * KP + k0 + cc * 4];
            *(float4*)&sB2[r * SSTR + cc * 4] =
                *(const float4*)&Wt2[(size_t)(n0 + r) * KP + k0 + cc * 4];
        }
        __syncthreads();

#pragma unroll
        for (int k8 = 0; k8 < 4; ++k8) {
            int kc = k8 * 8 + tig;
            uint32_t af[4][4];
            // ---- sweep 1: a_hi * (w_hi + w_lo) ----
#pragma unroll
            for (int mf = 0; mf < 4; ++mf) {
                int mr = wm * 64 + mf * 16 + g;
                af[mf][0] = __float_as_uint(sA1[mr * SSTR + kc]);
                af[mf][1] = __float_as_uint(sA1[(mr + 8) * SSTR + kc]);
                af[mf][2] = __float_as_uint(sA1[mr * SSTR + kc + 4]);
                af[mf][3] = __float_as_uint(sA1[(mr + 8) * SSTR + kc + 4]);
            }
#pragma unroll
            for (int nf = 0; nf < 5; ++nf) {
                int nr = wn * 40 + nf * 8 + g;
                uint32_t b10 = __float_as_uint(sB1[nr * SSTR + kc]);
                uint32_t b11 = __float_as_uint(sB1[nr * SSTR + kc + 4]);
                uint32_t b20 = __float_as_uint(sB2[nr * SSTR + kc]);
                uint32_t b21 = __float_as_uint(sB2[nr * SSTR + kc + 4]);
#pragma unroll
                for (int mf = 0; mf < 4; ++mf) {
                    mma_tf32(c[mf][nf], af[mf], b10, b11);
                    mma_tf32(c[mf][nf], af[mf], b20, b21);
                }
            }
            // ---- sweep 2: a_lo * w_hi ----
#pragma unroll
            for (int mf = 0; mf < 4; ++mf) {
                int mr = wm * 64 + mf * 16 + g;
                af[mf][0] = __float_as_uint(sA2[mr * SSTR + kc]);
                af[mf][1] = __float_as_uint(sA2[(mr + 8) * SSTR + kc]);
                af[mf][2] = __float_as_uint(sA2[mr * SSTR + kc + 4]);
                af[mf][3] = __float_as_uint(sA2[(mr + 8) * SSTR + kc + 4]);
            }
#pragma unroll
            for (int nf = 0; nf < 5; ++nf) {
                int nr = wn * 40 + nf * 8 + g;
                uint32_t b10 = __float_as_uint(sB1[nr * SSTR + kc]);
                uint32_t b11 = __float_as_uint(sB1[nr * SSTR + kc + 4]);
#pragma unroll
                for (int mf = 0; mf < 4; ++mf)
                    mma_tf32(c[mf][nf], af[mf], b10, b11);
            }
        }
        __syncthreads();
    }

    // epilogue: raw C to global
#pragma unroll
    for (int mf = 0; mf < 4; ++mf) {
#pragma unroll
        for (int nf = 0; nf < 5; ++nf) {
            int row = b0 + wm * 64 + mf * 16 + g;
            int col = n0 + wn * 40 + nf * 8 + 2 * tig;
            *(float2*)&C[(size_t)row * N + col] = make_float2(c[mf][nf][0], c[mf][nf][1]);
            *(float2*)&C[(size_t)(row + 8) * N + col] = make_float2(c[mf][nf][2], c[mf][nf][3]);
        }
    }
}

// ---------------- GRU combine: nonlinearity + split emit --------------------
__global__ void k_gruc(int v, const int* __restrict__ types, const int* __restrict__ paths,
                       const float* __restrict__ W_ih,
                       const float* __restrict__ b_ih, const float* __restrict__ b_hh)
{
    int idx = blockIdx.x * blockDim.x + threadIdx.x;
    if (idx >= BB * KP) return;
    int b = idx / KP, j = idx - b * KP;
    if (j >= HID) { d_A1[idx] = 0.f; d_A2[idx] = 0.f; return; }
    float rp = d_C[(size_t)b * 960 + j];
    float zp = d_C[(size_t)b * 960 + 320 + j];
    float np = d_C[(size_t)b * 960 + 640 + j];
    int t = types[b * MAXN + v], p = paths[b * MAXN + v];
    const float* wr_row = W_ih + j * 19;
    const float* wz_row = W_ih + (j + HID) * 19;
    const float* wn_row = W_ih + (j + 2*HID) * 19;
    float ir  = wr_row[t] + wr_row[NT + p] + b_ih[j];
    float iz  = wz_row[t] + wz_row[NT + p] + b_ih[j + HID];
    float inn = wn_row[t] + wn_row[NT + p] + b_ih[j + 2*HID];
    float r = sigm(ir + rp + b_hh[j]);
    float z = sigm(iz + zp + b_hh[j + HID]);
    float n = tanhf(inn + r * (np + b_hh[j + 2*HID]));
    float hi_ = d_hin[idx];
    float h = (1.f - z) * n + z * hi_;
    d_hcur[idx] = h;
    float hh, hl; tf32split(h, hh, hl);
    d_A1[idx] = hh; d_A2[idx] = hl;
}

// ---------------- gate combine ----------------------------------------------
__global__ void k_gatec(int v, const int* __restrict__ paths,
                        const float* __restrict__ Wg, const float* __restrict__ bg,
                        const float* __restrict__ Wm)
{
    int idx = blockIdx.x * blockDim.x + threadIdx.x;
    if (idx >= BB * HID) return;
    int b = idx / HID, j = idx - b * HID;
    float gp = d_C[(size_t)b * 640 + j];
    float mp = d_C[(size_t)b * 640 + 320 + j];
    int p = paths[b * MAXN + v];
    float gv = sigm(gp + Wg[j * VSTAT + HID + p] + bg[j]);
    float mv = mp + Wm[j * VSTAT + HID + p];
    d_g[((size_t)b * 11 + v) * KP + j] = gv * mv;
}

// ---------------- head ------------------------------------------------------
__global__ void __launch_bounds__(128) k_head(
    const int* __restrict__ paths, const float* __restrict__ feats,
    const float* __restrict__ W_df1, const float* __restrict__ b_df1,
    const float* __restrict__ W_df2, const float* __restrict__ b_df2,
    const float* __restrict__ W_fc1, const float* __restrict__ b_fc1,
    const float* __restrict__ W_fc2, const float* __restrict__ b_fc2,
    float* __restrict__ out)
{
    int b = blockIdx.x;
    int t = threadIdx.x;
    __shared__ float hg[HID + 8];
    __shared__ float df[3 * PP];
    __shared__ float hid16[16];

    for (int j = t; j < HID; j += 128) hg[j] = d_hcur[(size_t)b * KP + j];
    if (t < 3 * PP) df[t] = 0.f;
    __syncthreads();
    if (t == 0) {
        for (int v = 0; v < MAXN; ++v) {
            int base = paths[b * MAXN + v] * 3;
            df[base]     = feats[(b * MAXN + v) * 3 + 0];
            df[base + 1] = feats[(b * MAXN + v) * 3 + 1];
            df[base + 2] = feats[(b * MAXN + v) * 3 + 2];
        }
    }
    __syncthreads();
    if (t < 16) {
        float a = b_df1[t];
        for (int k = 0; k < 3 * PP; ++k) a = fmaf(df[k], W_df1[t * (3 * PP) + k], a);
        hid16[t] = fmaxf(a, 0.f);
    }
    __syncthreads();
    if (t < 8) {
        float a = b_df2[t];
        for (int k = 0; k < 16; ++k) a = fmaf(hid16[k], W_df2[t * 16 + k], a);
        hg[HID + t] = a;
    }
    __syncthreads();
    if (t < 112) {
        const float* W;
        float a;
        int i;
        if (t < 56) { i = t;      W = W_fc1; a = b_fc1[i]; }
        else        { i = t - 56; W = W_fc2; a = b_fc2[i]; }
        const float* wrow = W + i * (HID + 8);
        for (int k = 0; k < HID + 8; ++k) a = fmaf(hg[k], wrow[k], a);
        out[b * 112 + t] = a;
    }
}

// ---------------- launcher --------------------------------------------------
extern "C" void kernel_launch(void* const* d_in, const int* in_sizes, int n_in,
                              void* d_out, int out_size)
{
    const int*   types = (const int*)d_in[0];
    const int*   paths = (const int*)d_in[1];
    const int*   adj   = (const int*)d_in[2];
    const float* feats = (const float*)d_in[3];
    const float* W_ih  = (const float*)d_in[4];
    const float* W_hh  = (const float*)d_in[5];
    const float* b_ih  = (const float*)d_in[6];
    const float* b_hh  = (const float*)d_in[7];
    const float* Wg    = (const float*)d_in[8];
    const float* bg    = (const float*)d_in[9];
    const float* Wm    = (const float*)d_in[10];
    const float* W_df1 = (const float*)d_in[11];
    const float* b_df1 = (const float*)d_in[12];
    const float* W_df2 = (const float*)d_in[13];
    const float* b_df2 = (const float*)d_in[14];
    const float* W_fc1 = (const float*)d_in[15];
    const float* b_fc1 = (const float*)d_in[16];
    const float* W_fc2 = (const float*)d_in[17];
    const float* b_fc2 = (const float*)d_in[18];
    float* out = (float*)d_out;

    cudaFuncSetAttribute(k_gemm, cudaFuncAttributeMaxDynamicSharedMemorySize, SMEM_BYTES);

    float *pWhh1, *pWhh2, *pWgm1, *pWgm2, *pC;
    cudaGetSymbolAddress((void**)&pWhh1, d_Whh1);
    cudaGetSymbolAddress((void**)&pWhh2, d_Whh2);
    cudaGetSymbolAddress((void**)&pWgm1, d_Wgm1);
    cudaGetSymbolAddress((void**)&pWgm2, d_Wgm2);
    cudaGetSymbolAddress((void**)&pC,    d_C);

    dim3 gGru(BB / BM, 960 / BN);   // 32 x 6
    dim3 gGate(BB / BM, 640 / BN);  // 32 x 4

    k_pad<<<(5 * HID * HID + 255) / 256, 256>>>(W_hh, Wg, Wm);
    k_h0<<<(BB * HID + 255) / 256, 256>>>(types, paths, W_ih, b_ih, b_hh);

    k_gemm<<<gGate, 256, SMEM_BYTES>>>(pWgm1, pWgm2, pC, 640);
    k_gatec<<<(BB * HID + 255) / 256, 256>>>(0, paths, Wg, bg, Wm);

    for (int v = 1; v < MAXN; ++v) {
        k_hin<<<BB / 4, 4 * KP4>>>(adj, v);
        k_gemm<<<gGru, 256, SMEM_BYTES>>>(pWhh1, pWhh2, pC, 960);
        k_gruc<<<(BB * KP + 255) / 256, 256>>>(v, types, paths, W_ih, b_ih, b_hh);
        if (v < MAXN - 1) {
            k_gemm<<<gGate, 256, SMEM_BYTES>>>(pWgm1, pWgm2, pC, 640);
            k_gatec<<<(BB * HID + 255) / 256, 256>>>(v, paths, Wg, bg, Wm);
        }
    }
    k_head<<<BB, 128>>>(paths, feats, W_df1, b_df1, W_df2, b_df2,
                        W_fc1, b_fc1, W_fc2, b_fc2, out);
}